// round 2
// baseline (speedup 1.0000x reference)
#include <cuda_runtime.h>
#include <math.h>

#define B_ 64
#define T_ 512
#define I_ 256
#define H_ 1024
#define G_ 4096
#define O_ 256

// -------- device scratch (static: no allocations allowed) --------
__device__ float g_xproj0[(size_t)T_ * B_ * G_];   // [t][b][4H]
__device__ float g_xproj1[(size_t)T_ * B_ * G_];
__device__ float g_hseq0[(size_t)T_ * B_ * H_];    // [t][b][H]
__device__ float g_hseq1[(size_t)T_ * B_ * H_];
__device__ float g_hbuf[2][B_ * H_];               // double-buffered h
__device__ unsigned int g_arrive;

// -------- init: reset barrier counter + zero h buffers ----------
__global__ void init_kernel() {
    int idx = blockIdx.x * blockDim.x + threadIdx.x;
    if (idx == 0) g_arrive = 0u;
    float* p = (float*)g_hbuf;
    for (int i = idx; i < 2 * B_ * H_; i += gridDim.x * blockDim.x) p[i] = 0.f;
}

// -------- software grid barrier (all 128 blocks co-resident) ----
__device__ __forceinline__ void gridbar(unsigned int* target) {
    __threadfence();
    __syncthreads();
    if (threadIdx.x == 0) {
        atomicAdd(&g_arrive, 1u);
        *target += gridDim.x;
        unsigned int v;
        for (;;) {
            asm volatile("ld.acquire.gpu.u32 %0, [%1];" : "=r"(v) : "l"(&g_arrive) : "memory");
            if (v >= *target) break;
            __nanosleep(64);
        }
    }
    __syncthreads();
}

// -------- tiled fp32 GEMM: C[m][n] = A_row(m) . W[n][:] + b1[n]+b2[n]
// M = B*T (row m = t*B + b), N = 4096.
// mode 0: A = x [B][T][I]  (row ptr computed from (t,b))
// mode 1: A = hseq [T][B][H] (row ptr = A + m*H)
__global__ __launch_bounds__(256) void gemm_xproj(
    const float* __restrict__ A, const float* __restrict__ W,
    const float* __restrict__ b1, const float* __restrict__ b2,
    float* __restrict__ Cout, int K, int mode)
{
    __shared__ float sA[16][68];
    __shared__ float sB[16][68];

    int tid = threadIdx.x;
    int n0 = blockIdx.x * 64;
    int m0 = blockIdx.y * 64;

    int tm = (tid / 16) * 4;
    int tn = (tid % 16) * 4;

    float acc[4][4];
#pragma unroll
    for (int i = 0; i < 4; i++)
#pragma unroll
        for (int j = 0; j < 4; j++) acc[i][j] = 0.f;

    // each thread loads one float4 of A tile and one of B tile per k-step
    int lrow = m0 + (tid >> 2);
    const float* arow;
    if (mode == 0) {
        int t = lrow >> 6, b = lrow & 63;
        arow = A + ((size_t)b * T_ + t) * I_;
    } else {
        arow = A + (size_t)lrow * H_;
    }
    int lka = (tid & 3) * 4;
    int mm = tid >> 2;
    const float* brow = W + (size_t)(n0 + mm) * K;

    for (int k0 = 0; k0 < K; k0 += 16) {
        float4 av = *(const float4*)(arow + k0 + lka);
        float4 bv = *(const float4*)(brow + k0 + lka);
        __syncthreads();
        sA[lka + 0][mm] = av.x; sA[lka + 1][mm] = av.y;
        sA[lka + 2][mm] = av.z; sA[lka + 3][mm] = av.w;
        sB[lka + 0][mm] = bv.x; sB[lka + 1][mm] = bv.y;
        sB[lka + 2][mm] = bv.z; sB[lka + 3][mm] = bv.w;
        __syncthreads();
#pragma unroll
        for (int kk = 0; kk < 16; kk++) {
            float4 a4 = *(const float4*)&sA[kk][tm];
            float4 b4 = *(const float4*)&sB[kk][tn];
            float av_[4] = {a4.x, a4.y, a4.z, a4.w};
            float bv_[4] = {b4.x, b4.y, b4.z, b4.w};
#pragma unroll
            for (int i = 0; i < 4; i++)
#pragma unroll
                for (int j = 0; j < 4; j++)
                    acc[i][j] += av_[i] * bv_[j];
        }
    }

#pragma unroll
    for (int i = 0; i < 4; i++) {
        size_t rbase = (size_t)(m0 + tm + i) * G_;
#pragma unroll
        for (int j = 0; j < 4; j++) {
            int n = n0 + tn + j;
            Cout[rbase + n] = acc[i][j] + b1[n] + b2[n];
        }
    }
}

// -------- persistent LSTM recurrence --------------------------------
// 128 blocks; block bk owns h-columns j = bk*8 .. bk*8+7 across ALL 4 gates
// (gate cols q*1024 + j), so the cell update is block-local. c lives in smem.
__global__ __launch_bounds__(256) void lstm_recur(
    const float* __restrict__ xproj,   // [T][B][4H]
    const float* __restrict__ Whh,     // [4H][H]
    float* __restrict__ hseq)          // [T][B][H]
{
    __shared__ float sH[B_ * 64];       // 64 b x 64 k chunk   (16 KB)
    __shared__ float sWT[64 * 34];      // k x 32 gate-cols, padded (8.5 KB)
    __shared__ float sG[B_ * 32];       // gates for this block (8 KB)
    __shared__ float sC[B_ * 8];        // persistent cell state (2 KB)

    int tid = threadIdx.x;
    int jbase = blockIdx.x * 8;

    for (int i = tid; i < B_ * 8; i += 256) sC[i] = 0.f;

    // compute mapping: 2 gate-cols x 4 batch rows per thread
    int c0 = (tid & 15) * 2;            // 0..30 (even)
    int brow0 = (tid >> 4) * 4;         // 0..60
    int q0 = c0 >> 3;
    int jj0 = c0 & 7;                   // even, jj0+1 same gate

    // W loading mapping: this thread loads gate-col lc, k-range lkb..lkb+7
    int lc = tid & 31;
    int lkb = (tid >> 5) * 8;
    const float* wr = Whh + ((size_t)((lc >> 3) * H_ + jbase + (lc & 7))) * H_ + lkb;

    unsigned int target = 0;
    __syncthreads();

    for (int t = 0; t < T_; t++) {
        const float* hread = g_hbuf[t & 1];
        float* hwrite = g_hbuf[(t + 1) & 1];

        float acc[4][2];
#pragma unroll
        for (int r = 0; r < 4; r++) { acc[r][0] = 0.f; acc[r][1] = 0.f; }

        for (int kc = 0; kc < H_; kc += 64) {
            // load h chunk: 64 b x 64 k
#pragma unroll
            for (int u = 0; u < 4; u++) {
                int f4 = tid + 256 * u;
                int b = f4 >> 4;
                int kk = (f4 & 15) << 2;
                float4 v = *(const float4*)(hread + b * H_ + kc + kk);
                *(float4*)&sH[b * 64 + kk] = v;
            }
            // load W chunk transposed: sWT[k][c]
            {
                float4 w0 = *(const float4*)(wr + kc);
                float4 w1 = *(const float4*)(wr + kc + 4);
                sWT[(lkb + 0) * 34 + lc] = w0.x;
                sWT[(lkb + 1) * 34 + lc] = w0.y;
                sWT[(lkb + 2) * 34 + lc] = w0.z;
                sWT[(lkb + 3) * 34 + lc] = w0.w;
                sWT[(lkb + 4) * 34 + lc] = w1.x;
                sWT[(lkb + 5) * 34 + lc] = w1.y;
                sWT[(lkb + 6) * 34 + lc] = w1.z;
                sWT[(lkb + 7) * 34 + lc] = w1.w;
            }
            __syncthreads();
#pragma unroll 8
            for (int k = 0; k < 64; k++) {
                float2 w = *(const float2*)&sWT[k * 34 + c0];
#pragma unroll
                for (int r = 0; r < 4; r++) {
                    float hv = sH[(brow0 + r) * 64 + k];
                    acc[r][0] += hv * w.x;
                    acc[r][1] += hv * w.y;
                }
            }
            __syncthreads();
        }

        // add xproj, stash gates in smem
#pragma unroll
        for (int r = 0; r < 4; r++) {
            int b = brow0 + r;
            size_t xbase = ((size_t)t * B_ + b) * G_;
            float2 xp = *(const float2*)(xproj + xbase + q0 * H_ + jbase + jj0);
            sG[b * 32 + c0]     = acc[r][0] + xp.x;
            sG[b * 32 + c0 + 1] = acc[r][1] + xp.y;
        }
        __syncthreads();

        // cell update: 512 cells / block, 2 per thread
#pragma unroll
        for (int u = 0; u < 2; u++) {
            int id = tid + 256 * u;
            int b = id >> 3, jj = id & 7;
            float iv = sG[b * 32 + jj];
            float fv = sG[b * 32 + 8 + jj];
            float gv = sG[b * 32 + 16 + jj];
            float ov = sG[b * 32 + 24 + jj];
            float ig = 1.f / (1.f + expf(-iv));
            float fg = 1.f / (1.f + expf(-fv));
            float gg = tanhf(gv);
            float og = 1.f / (1.f + expf(-ov));
            float cc = fg * sC[b * 8 + jj] + ig * gg;
            sC[b * 8 + jj] = cc;
            float hh = og * tanhf(cc);
            hwrite[b * H_ + jbase + jj] = hh;
            hseq[((size_t)t * B_ + b) * H_ + jbase + jj] = hh;
        }

        gridbar(&target);
    }
}

// -------- FC head: out[b][o] = h_last[b] . fc_w[o] + fc_b[o] --------
__global__ __launch_bounds__(256) void fc_kernel(
    const float* __restrict__ fc_w, const float* __restrict__ fc_b,
    float* __restrict__ out)
{
    __shared__ float sh[H_];
    int b = blockIdx.x, tid = threadIdx.x;
    const float* hlast = g_hseq1 + ((size_t)(T_ - 1) * B_ + b) * H_;
    for (int i = tid; i < H_; i += 256) sh[i] = hlast[i];
    __syncthreads();
    int o = tid;
    const float* wrow = fc_w + (size_t)o * H_;
    float acc = fc_b[o];
#pragma unroll 8
    for (int k = 0; k < H_; k++) acc += sh[k] * wrow[k];
    out[b * O_ + o] = acc;
}

// -------- launch --------------------------------------------------
extern "C" void kernel_launch(void* const* d_in, const int* in_sizes, int n_in,
                              void* d_out, int out_size) {
    (void)in_sizes; (void)n_in; (void)out_size;
    const float* x     = (const float*)d_in[0];
    const float* W_ih0 = (const float*)d_in[1];
    const float* W_hh0 = (const float*)d_in[2];
    const float* b_ih0 = (const float*)d_in[3];
    const float* b_hh0 = (const float*)d_in[4];
    const float* W_ih1 = (const float*)d_in[5];
    const float* W_hh1 = (const float*)d_in[6];
    const float* b_ih1 = (const float*)d_in[7];
    const float* b_hh1 = (const float*)d_in[8];
    const float* fc_w  = (const float*)d_in[9];
    const float* fc_b  = (const float*)d_in[10];
    float* out = (float*)d_out;

    float *xp0, *xp1, *hs0, *hs1;
    cudaGetSymbolAddress((void**)&xp0, g_xproj0);
    cudaGetSymbolAddress((void**)&xp1, g_xproj1);
    cudaGetSymbolAddress((void**)&hs0, g_hseq0);
    cudaGetSymbolAddress((void**)&hs1, g_hseq1);

    dim3 ggrid(G_ / 64, (B_ * T_) / 64);

    // layer 0
    gemm_xproj<<<ggrid, 256>>>(x, W_ih0, b_ih0, b_hh0, xp0, I_, 0);
    init_kernel<<<64, 256>>>();
    lstm_recur<<<128, 256>>>(xp0, W_hh0, hs0);

    // layer 1
    gemm_xproj<<<ggrid, 256>>>(hs0, W_ih1, b_ih1, b_hh1, xp1, H_, 1);
    init_kernel<<<64, 256>>>();
    lstm_recur<<<128, 256>>>(xp1, W_hh1, hs1);

    // head
    fc_kernel<<<64, 256>>>(fc_w, fc_b, out);
}

// round 3
// speedup vs baseline: 1.0018x; 1.0018x over previous
#include <cuda_runtime.h>
#include <math.h>

#define B_ 64
#define T_ 512
#define I_ 256
#define H_ 1024
#define G_ 4096
#define O_ 256

// -------- device scratch (static: no allocations allowed) --------
__device__ float g_xproj0[(size_t)T_ * B_ * G_];   // [t][b][4H]
__device__ float g_xproj1[(size_t)T_ * B_ * G_];
__device__ float g_hseq0[(size_t)T_ * B_ * H_];    // [t][b][H]
__device__ float g_hseq1[(size_t)T_ * B_ * H_];
__device__ float g_hbuf[2][B_ * H_];               // double-buffered h
__device__ unsigned int g_arrive;

// -------- init: reset barrier counter + zero h buffers ----------
__global__ void init_kernel() {
    int idx = blockIdx.x * blockDim.x + threadIdx.x;
    if (idx == 0) g_arrive = 0u;
    float* p = (float*)g_hbuf;
    for (int i = idx; i < 2 * B_ * H_; i += gridDim.x * blockDim.x) p[i] = 0.f;
}

// -------- software grid barrier (all 128 blocks co-resident) ----
__device__ __forceinline__ void gridbar(unsigned int* target) {
    __threadfence();
    __syncthreads();
    if (threadIdx.x == 0) {
        atomicAdd(&g_arrive, 1u);
        *target += gridDim.x;
        unsigned int v;
        for (;;) {
            asm volatile("ld.acquire.gpu.u32 %0, [%1];" : "=r"(v) : "l"(&g_arrive) : "memory");
            if (v >= *target) break;
            __nanosleep(64);
        }
    }
    __syncthreads();
}

// -------- tiled fp32 GEMM: C[m][n] = A_row(m) . W[n][:] + b1[n]+b2[n]
// M = B*T (row m = t*B + b), N = 4096.
// mode 0: A = x [B][T][I]  (row ptr computed from (t,b))
// mode 1: A = hseq [T][B][H] (row ptr = A + m*H)
__global__ __launch_bounds__(256) void gemm_xproj(
    const float* __restrict__ A, const float* __restrict__ W,
    const float* __restrict__ b1, const float* __restrict__ b2,
    float* __restrict__ Cout, int K, int mode)
{
    __shared__ float sA[16][68];
    __shared__ float sB[16][68];

    int tid = threadIdx.x;
    int n0 = blockIdx.x * 64;
    int m0 = blockIdx.y * 64;

    int tm = (tid / 16) * 4;
    int tn = (tid % 16) * 4;

    float acc[4][4];
#pragma unroll
    for (int i = 0; i < 4; i++)
#pragma unroll
        for (int j = 0; j < 4; j++) acc[i][j] = 0.f;

    // each thread loads one float4 of A tile and one of B tile per k-step
    int lrow = m0 + (tid >> 2);
    const float* arow;
    if (mode == 0) {
        int t = lrow >> 6, b = lrow & 63;
        arow = A + ((size_t)b * T_ + t) * I_;
    } else {
        arow = A + (size_t)lrow * H_;
    }
    int lka = (tid & 3) * 4;
    int mm = tid >> 2;
    const float* brow = W + (size_t)(n0 + mm) * K;

    for (int k0 = 0; k0 < K; k0 += 16) {
        float4 av = *(const float4*)(arow + k0 + lka);
        float4 bv = *(const float4*)(brow + k0 + lka);
        __syncthreads();
        sA[lka + 0][mm] = av.x; sA[lka + 1][mm] = av.y;
        sA[lka + 2][mm] = av.z; sA[lka + 3][mm] = av.w;
        sB[lka + 0][mm] = bv.x; sB[lka + 1][mm] = bv.y;
        sB[lka + 2][mm] = bv.z; sB[lka + 3][mm] = bv.w;
        __syncthreads();
#pragma unroll
        for (int kk = 0; kk < 16; kk++) {
            float4 a4 = *(const float4*)&sA[kk][tm];
            float4 b4 = *(const float4*)&sB[kk][tn];
            float av_[4] = {a4.x, a4.y, a4.z, a4.w};
            float bv_[4] = {b4.x, b4.y, b4.z, b4.w};
#pragma unroll
            for (int i = 0; i < 4; i++)
#pragma unroll
                for (int j = 0; j < 4; j++)
                    acc[i][j] += av_[i] * bv_[j];
        }
    }

#pragma unroll
    for (int i = 0; i < 4; i++) {
        size_t rbase = (size_t)(m0 + tm + i) * G_;
#pragma unroll
        for (int j = 0; j < 4; j++) {
            int n = n0 + tn + j;
            Cout[rbase + n] = acc[i][j] + b1[n] + b2[n];
        }
    }
}

// -------- persistent LSTM recurrence --------------------------------
// 128 blocks; block bk owns h-columns j = bk*8 .. bk*8+7 across ALL 4 gates
// (gate cols q*1024 + j), so the cell update is block-local. c lives in smem.
__global__ __launch_bounds__(256) void lstm_recur(
    const float* __restrict__ xproj,   // [T][B][4H]
    const float* __restrict__ Whh,     // [4H][H]
    float* __restrict__ hseq)          // [T][B][H]
{
    __shared__ float sH[B_ * 64];       // 64 b x 64 k chunk   (16 KB)
    __shared__ float sWT[64 * 34];      // k x 32 gate-cols, padded (8.5 KB)
    __shared__ float sG[B_ * 32];       // gates for this block (8 KB)
    __shared__ float sC[B_ * 8];        // persistent cell state (2 KB)

    int tid = threadIdx.x;
    int jbase = blockIdx.x * 8;

    for (int i = tid; i < B_ * 8; i += 256) sC[i] = 0.f;

    // compute mapping: 2 gate-cols x 4 batch rows per thread
    int c0 = (tid & 15) * 2;            // 0..30 (even)
    int brow0 = (tid >> 4) * 4;         // 0..60
    int q0 = c0 >> 3;
    int jj0 = c0 & 7;                   // even, jj0+1 same gate

    // W loading mapping: this thread loads gate-col lc, k-range lkb..lkb+7
    int lc = tid & 31;
    int lkb = (tid >> 5) * 8;
    const float* wr = Whh + ((size_t)((lc >> 3) * H_ + jbase + (lc & 7))) * H_ + lkb;

    unsigned int target = 0;
    __syncthreads();

    for (int t = 0; t < T_; t++) {
        const float* hread = g_hbuf[t & 1];
        float* hwrite = g_hbuf[(t + 1) & 1];

        float acc[4][2];
#pragma unroll
        for (int r = 0; r < 4; r++) { acc[r][0] = 0.f; acc[r][1] = 0.f; }

        for (int kc = 0; kc < H_; kc += 64) {
            // load h chunk: 64 b x 64 k
#pragma unroll
            for (int u = 0; u < 4; u++) {
                int f4 = tid + 256 * u;
                int b = f4 >> 4;
                int kk = (f4 & 15) << 2;
                float4 v = *(const float4*)(hread + b * H_ + kc + kk);
                *(float4*)&sH[b * 64 + kk] = v;
            }
            // load W chunk transposed: sWT[k][c]
            {
                float4 w0 = *(const float4*)(wr + kc);
                float4 w1 = *(const float4*)(wr + kc + 4);
                sWT[(lkb + 0) * 34 + lc] = w0.x;
                sWT[(lkb + 1) * 34 + lc] = w0.y;
                sWT[(lkb + 2) * 34 + lc] = w0.z;
                sWT[(lkb + 3) * 34 + lc] = w0.w;
                sWT[(lkb + 4) * 34 + lc] = w1.x;
                sWT[(lkb + 5) * 34 + lc] = w1.y;
                sWT[(lkb + 6) * 34 + lc] = w1.z;
                sWT[(lkb + 7) * 34 + lc] = w1.w;
            }
            __syncthreads();
#pragma unroll 8
            for (int k = 0; k < 64; k++) {
                float2 w = *(const float2*)&sWT[k * 34 + c0];
#pragma unroll
                for (int r = 0; r < 4; r++) {
                    float hv = sH[(brow0 + r) * 64 + k];
                    acc[r][0] += hv * w.x;
                    acc[r][1] += hv * w.y;
                }
            }
            __syncthreads();
        }

        // add xproj, stash gates in smem
#pragma unroll
        for (int r = 0; r < 4; r++) {
            int b = brow0 + r;
            size_t xbase = ((size_t)t * B_ + b) * G_;
            float2 xp = *(const float2*)(xproj + xbase + q0 * H_ + jbase + jj0);
            sG[b * 32 + c0]     = acc[r][0] + xp.x;
            sG[b * 32 + c0 + 1] = acc[r][1] + xp.y;
        }
        __syncthreads();

        // cell update: 512 cells / block, 2 per thread
#pragma unroll
        for (int u = 0; u < 2; u++) {
            int id = tid + 256 * u;
            int b = id >> 3, jj = id & 7;
            float iv = sG[b * 32 + jj];
            float fv = sG[b * 32 + 8 + jj];
            float gv = sG[b * 32 + 16 + jj];
            float ov = sG[b * 32 + 24 + jj];
            float ig = 1.f / (1.f + expf(-iv));
            float fg = 1.f / (1.f + expf(-fv));
            float gg = tanhf(gv);
            float og = 1.f / (1.f + expf(-ov));
            float cc = fg * sC[b * 8 + jj] + ig * gg;
            sC[b * 8 + jj] = cc;
            float hh = og * tanhf(cc);
            hwrite[b * H_ + jbase + jj] = hh;
            hseq[((size_t)t * B_ + b) * H_ + jbase + jj] = hh;
        }

        gridbar(&target);
    }
}

// -------- FC head: out[b][o] = h_last[b] . fc_w[o] + fc_b[o] --------
__global__ __launch_bounds__(256) void fc_kernel(
    const float* __restrict__ fc_w, const float* __restrict__ fc_b,
    float* __restrict__ out)
{
    __shared__ float sh[H_];
    int b = blockIdx.x, tid = threadIdx.x;
    const float* hlast = g_hseq1 + ((size_t)(T_ - 1) * B_ + b) * H_;
    for (int i = tid; i < H_; i += 256) sh[i] = hlast[i];
    __syncthreads();
    int o = tid;
    const float* wrow = fc_w + (size_t)o * H_;
    float acc = fc_b[o];
#pragma unroll 8
    for (int k = 0; k < H_; k++) acc += sh[k] * wrow[k];
    out[b * O_ + o] = acc;
}

// -------- launch --------------------------------------------------
extern "C" void kernel_launch(void* const* d_in, const int* in_sizes, int n_in,
                              void* d_out, int out_size) {
    (void)in_sizes; (void)n_in; (void)out_size;
    const float* x     = (const float*)d_in[0];
    const float* W_ih0 = (const float*)d_in[1];
    const float* W_hh0 = (const float*)d_in[2];
    const float* b_ih0 = (const float*)d_in[3];
    const float* b_hh0 = (const float*)d_in[4];
    const float* W_ih1 = (const float*)d_in[5];
    const float* W_hh1 = (const float*)d_in[6];
    const float* b_ih1 = (const float*)d_in[7];
    const float* b_hh1 = (const float*)d_in[8];
    const float* fc_w  = (const float*)d_in[9];
    const float* fc_b  = (const float*)d_in[10];
    float* out = (float*)d_out;

    float *xp0, *xp1, *hs0, *hs1;
    cudaGetSymbolAddress((void**)&xp0, g_xproj0);
    cudaGetSymbolAddress((void**)&xp1, g_xproj1);
    cudaGetSymbolAddress((void**)&hs0, g_hseq0);
    cudaGetSymbolAddress((void**)&hs1, g_hseq1);

    dim3 ggrid(G_ / 64, (B_ * T_) / 64);

    // layer 0
    gemm_xproj<<<ggrid, 256>>>(x, W_ih0, b_ih0, b_hh0, xp0, I_, 0);
    init_kernel<<<64, 256>>>();
    lstm_recur<<<128, 256>>>(xp0, W_hh0, hs0);

    // layer 1
    gemm_xproj<<<ggrid, 256>>>(hs0, W_ih1, b_ih1, b_hh1, xp1, H_, 1);
    init_kernel<<<64, 256>>>();
    lstm_recur<<<128, 256>>>(xp1, W_hh1, hs1);

    // head
    fc_kernel<<<64, 256>>>(fc_w, fc_b, out);
}

// round 5
// speedup vs baseline: 2.1088x; 2.1051x over previous
#include <cuda_runtime.h>
#include <cuda_bf16.h>
#include <stdint.h>
#include <math.h>

#define B_ 64
#define T_ 512
#define I_ 256
#define H_ 1024
#define G_ 4096
#define O_ 256

// ---------------- device scratch ----------------
__device__ float g_xproj0[(size_t)T_ * B_ * G_];   // [t][b][4H] fp32
__device__ float g_xproj1[(size_t)T_ * B_ * G_];
__device__ __nv_bfloat16 g_xhi[(size_t)B_ * T_ * I_];
__device__ __nv_bfloat16 g_xlo[(size_t)B_ * T_ * I_];
__device__ __nv_bfloat16 g_wih0hi[(size_t)G_ * I_];
__device__ __nv_bfloat16 g_wih0lo[(size_t)G_ * I_];
__device__ __nv_bfloat16 g_wih1hi[(size_t)G_ * H_];
__device__ __nv_bfloat16 g_wih1lo[(size_t)G_ * H_];
__device__ __nv_bfloat16 g_hs0hi[(size_t)T_ * B_ * H_];  // layer-0 outputs hi/lo
__device__ __nv_bfloat16 g_hs0lo[(size_t)T_ * B_ * H_];
__device__ __nv_bfloat16 g_hhi[2][B_ * H_];
__device__ __nv_bfloat16 g_hlo[2][B_ * H_];
__device__ float g_hlast[B_ * H_];                 // fp32 final h for FC
__device__ unsigned int g_arrive;

// ---------------- helpers ----------------
__device__ __forceinline__ void ldsm4(uint32_t* r, uint32_t addr) {
    asm volatile("ldmatrix.sync.aligned.m8n8.x4.shared.b16 {%0,%1,%2,%3}, [%4];"
        : "=r"(r[0]), "=r"(r[1]), "=r"(r[2]), "=r"(r[3]) : "r"(addr));
}
__device__ __forceinline__ void ldsm2(uint32_t* r, uint32_t addr) {
    asm volatile("ldmatrix.sync.aligned.m8n8.x2.shared.b16 {%0,%1}, [%2];"
        : "=r"(r[0]), "=r"(r[1]) : "r"(addr));
}
__device__ __forceinline__ void mma16816(float* c, const uint32_t* a, const uint32_t* b) {
    asm volatile("mma.sync.aligned.m16n8k16.row.col.f32.bf16.bf16.f32 "
        "{%0,%1,%2,%3}, {%4,%5,%6,%7}, {%8,%9}, {%0,%1,%2,%3};"
        : "+f"(c[0]), "+f"(c[1]), "+f"(c[2]), "+f"(c[3])
        : "r"(a[0]), "r"(a[1]), "r"(a[2]), "r"(a[3]), "r"(b[0]), "r"(b[1]));
}
__device__ __forceinline__ uint32_t cvta_s(const void* p) {
    return (uint32_t)__cvta_generic_to_shared(p);
}

// ---------------- init ----------------
__global__ void init_kernel() {
    int idx = blockIdx.x * blockDim.x + threadIdx.x;
    if (idx == 0) g_arrive = 0u;
    __nv_bfloat16 z = __float2bfloat16(0.f);
    int n = 2 * B_ * H_;
    __nv_bfloat16* ph = (__nv_bfloat16*)g_hhi;
    __nv_bfloat16* pl = (__nv_bfloat16*)g_hlo;
    for (int i = idx; i < n; i += gridDim.x * blockDim.x) { ph[i] = z; pl[i] = z; }
}

// ---------------- fp32 -> bf16 hi/lo split ----------------
__global__ void split_kernel(const float* __restrict__ src,
                             __nv_bfloat16* __restrict__ hi,
                             __nv_bfloat16* __restrict__ lo, int n4) {
    int i = blockIdx.x * blockDim.x + threadIdx.x;
    if (i >= n4) return;
    float4 v = ((const float4*)src)[i];
    __nv_bfloat16 h0 = __float2bfloat16(v.x);
    __nv_bfloat16 h1 = __float2bfloat16(v.y);
    __nv_bfloat16 h2 = __float2bfloat16(v.z);
    __nv_bfloat16 h3 = __float2bfloat16(v.w);
    __nv_bfloat162 a, b;
    a.x = h0; a.y = h1; b.x = h2; b.y = h3;
    ((__nv_bfloat162*)hi)[2 * i] = a;
    ((__nv_bfloat162*)hi)[2 * i + 1] = b;
    a.x = __float2bfloat16(v.x - __bfloat162float(h0));
    a.y = __float2bfloat16(v.y - __bfloat162float(h1));
    b.x = __float2bfloat16(v.z - __bfloat162float(h2));
    b.y = __float2bfloat16(v.w - __bfloat162float(h3));
    ((__nv_bfloat162*)lo)[2 * i] = a;
    ((__nv_bfloat162*)lo)[2 * i + 1] = b;
}

// ---------------- software grid barrier ----------------
__device__ __forceinline__ void gridbar(unsigned int* target) {
    __threadfence();
    __syncthreads();
    if (threadIdx.x == 0) {
        atomicAdd(&g_arrive, 1u);
        *target += gridDim.x;
        unsigned int v;
        for (;;) {
            asm volatile("ld.acquire.gpu.u32 %0, [%1];" : "=r"(v) : "l"(&g_arrive) : "memory");
            if (v >= *target) break;
            __nanosleep(64);
        }
    }
    __syncthreads();
}

// ---------------- split-bf16 MMA projection GEMM ----------------
// C[m][n] = A_row(m) . W[n][:] + b1[n] + b2[n],  M=B*T (m = t*B+b), N=4096.
// mode 0: A = x split [b][t][I]; mode 1: A = hseq split [m][H].
__global__ __launch_bounds__(256) void mma_xproj(
    const __nv_bfloat16* __restrict__ Ahi, const __nv_bfloat16* __restrict__ Alo,
    const __nv_bfloat16* __restrict__ Whi, const __nv_bfloat16* __restrict__ Wlo,
    const float* __restrict__ b1, const float* __restrict__ b2,
    float* __restrict__ Cout, int K, int mode)
{
    __shared__ __nv_bfloat16 sAhi[128 * 40], sAlo[128 * 40];
    __shared__ __nv_bfloat16 sBhi[64 * 40],  sBlo[64 * 40];
    __shared__ float sBias[64];

    int tid = threadIdx.x;
    int n0 = blockIdx.x * 64;
    int m0 = blockIdx.y * 128;
    int w = tid >> 5, lane = tid & 31;
    int r0 = w * 16;

    if (tid < 64) sBias[tid] = b1[n0 + tid] + b2[n0 + tid];

    float acc[8][4];
#pragma unroll
    for (int i = 0; i < 8; i++)
#pragma unroll
        for (int j = 0; j < 4; j++) acc[i][j] = 0.f;

    // A-tile load mapping: idx -> (row, 16B segment)
    size_t arow[2]; int aoff[2];
#pragma unroll
    for (int it = 0; it < 2; it++) {
        int idx = tid + it * 256;
        int r = idx >> 2, seg = idx & 3;
        int m = m0 + r;
        arow[it] = (mode == 0) ? ((size_t)(m & 63) * T_ + (size_t)(m >> 6)) * (size_t)K + (size_t)(seg * 8)
                               : (size_t)m * (size_t)K + (size_t)(seg * 8);
        aoff[it] = r * 40 + seg * 8;
    }
    int br = tid >> 2, bseg = tid & 3;
    size_t brow = (size_t)(n0 + br) * (size_t)K + (size_t)(bseg * 8);
    int boff = br * 40 + bseg * 8;

    // ldmatrix lane bases
    int lrA = (lane & 7) + (lane & 8);
    int lcA = (lane & 16) ? 8 : 0;
    uint32_t aHiB = cvta_s(&sAhi[(r0 + lrA) * 40 + lcA]);
    uint32_t aLoB = cvta_s(&sAlo[(r0 + lrA) * 40 + lcA]);
    int lrB = lane & 7;
    int lcB = (lane & 8) ? 8 : 0;
    uint32_t bHiB = cvta_s(&sBhi[lrB * 40 + lcB]);
    uint32_t bLoB = cvta_s(&sBlo[lrB * 40 + lcB]);

    for (int kc = 0; kc < K; kc += 32) {
        __syncthreads();
#pragma unroll
        for (int it = 0; it < 2; it++) {
            *(uint4*)&sAhi[aoff[it]] = *(const uint4*)(Ahi + arow[it] + kc);
            *(uint4*)&sAlo[aoff[it]] = *(const uint4*)(Alo + arow[it] + kc);
        }
        *(uint4*)&sBhi[boff] = *(const uint4*)(Whi + brow + kc);
        *(uint4*)&sBlo[boff] = *(const uint4*)(Wlo + brow + kc);
        __syncthreads();
#pragma unroll
        for (int ks = 0; ks < 2; ks++) {
            int k0 = ks * 16;
            uint32_t ah[4], al[4];
            ldsm4(ah, aHiB + (uint32_t)(k0 * 2));
            ldsm4(al, aLoB + (uint32_t)(k0 * 2));
#pragma unroll
            for (int nt = 0; nt < 8; nt++) {
                uint32_t bh[2], bl[2];
                uint32_t off = (uint32_t)(nt * 8 * 40 + k0) * 2u;
                ldsm2(bh, bHiB + off);
                ldsm2(bl, bLoB + off);
                mma16816(acc[nt], ah, bh);
                mma16816(acc[nt], ah, bl);
                mma16816(acc[nt], al, bh);
            }
        }
    }

    int g = lane >> 2, tq = lane & 3;
#pragma unroll
    for (int nt = 0; nt < 8; nt++) {
        int col = nt * 8 + tq * 2;
        float bb0 = sBias[col], bb1 = sBias[col + 1];
        size_t mA = (size_t)(m0 + r0 + g) * G_ + n0 + col;
        size_t mB = (size_t)(m0 + r0 + g + 8) * G_ + n0 + col;
        float2 v0 = make_float2(acc[nt][0] + bb0, acc[nt][1] + bb1);
        float2 v1 = make_float2(acc[nt][2] + bb0, acc[nt][3] + bb1);
        *(float2*)&Cout[mA] = v0;
        *(float2*)&Cout[mB] = v1;
    }
}

// ---------------- persistent LSTM recurrence (split-bf16 MMA) ----------------
// 128 blocks; block owns 8 h-columns across all 4 gates (32 gate-cols).
// W_hh split to bf16 hi/lo in SMEM once, resident for all 512 steps.
extern __shared__ char smem_dyn[];
__global__ __launch_bounds__(256) void lstm_recur_mma(
    const float* __restrict__ xproj,   // [T][B][4H] fp32
    const float* __restrict__ Whh,     // [4H][H] fp32
    __nv_bfloat16* __restrict__ hshi, __nv_bfloat16* __restrict__ hslo,
    int writeLast)
{
    __nv_bfloat16* sWhi = (__nv_bfloat16*)smem_dyn;        // 32 x 1032
    __nv_bfloat16* sWlo = sWhi + 32 * 1032;
    __nv_bfloat16* sHhi = sWlo + 32 * 1032;                // 64 x 136
    __nv_bfloat16* sHlo = sHhi + 64 * 136;
    float* sG = (float*)(sHlo + 64 * 136);                 // 64 x 32
    float* sC = sG + 64 * 32;                              // 64 x 8

    int tid = threadIdx.x, w = tid >> 5, lane = tid & 31;
    int jbase = blockIdx.x * 8;

    // load + split W_hh into SMEM (once)
    for (int i = tid; i < 32 * 1024; i += 256) {
        int n = i >> 10, k = i & 1023;
        float v = Whh[(size_t)((n >> 3) * H_ + jbase + (n & 7)) * H_ + k];
        __nv_bfloat16 hh = __float2bfloat16(v);
        sWhi[n * 1032 + k] = hh;
        sWlo[n * 1032 + k] = __float2bfloat16(v - __bfloat162float(hh));
    }
    for (int i = tid; i < 512; i += 256) sC[i] = 0.f;

    int r0 = (w & 3) * 16;   // batch-row group
    int cg = w >> 2;         // column group (0/1)
    int lrA = (lane & 7) + (lane & 8);
    int lcA = (lane & 16) ? 8 : 0;
    uint32_t aHiB = cvta_s(&sHhi[(r0 + lrA) * 136 + lcA]);
    uint32_t aLoB = cvta_s(&sHlo[(r0 + lrA) * 136 + lcA]);
    int lrB = lane & 7;
    int lcB = (lane & 8) ? 8 : 0;
    uint32_t bHiB = cvta_s(&sWhi[lrB * 1032 + lcB]);
    uint32_t bLoB = cvta_s(&sWlo[lrB * 1032 + lcB]);

    unsigned int target = 0;
    int g = lane >> 2, tq = lane & 3;

    for (int t = 0; t < T_; t++) {
        const __nv_bfloat16* hrH = g_hhi[t & 1];
        const __nv_bfloat16* hrL = g_hlo[t & 1];
        float acc[2][4];
#pragma unroll
        for (int i = 0; i < 2; i++)
#pragma unroll
            for (int j = 0; j < 4; j++) acc[i][j] = 0.f;

        for (int kc = 0; kc < H_; kc += 128) {
            __syncthreads();
#pragma unroll
            for (int it = 0; it < 4; it++) {
                int idx = tid + it * 256;
                int r = idx >> 4, seg = (idx & 15) * 8;
                *(uint4*)&sHhi[r * 136 + seg] = *(const uint4*)(hrH + r * H_ + kc + seg);
                *(uint4*)&sHlo[r * 136 + seg] = *(const uint4*)(hrL + r * H_ + kc + seg);
            }
            __syncthreads();
#pragma unroll
            for (int ks = 0; ks < 8; ks++) {
                int k0 = ks * 16;
                uint32_t ah[4], al[4];
                ldsm4(ah, aHiB + (uint32_t)(k0 * 2));
                ldsm4(al, aLoB + (uint32_t)(k0 * 2));
#pragma unroll
                for (int nt = 0; nt < 2; nt++) {
                    uint32_t bh[2], bl[2];
                    uint32_t off = (uint32_t)((cg * 2 + nt) * 8 * 1032 + kc + k0) * 2u;
                    ldsm2(bh, bHiB + off);
                    ldsm2(bl, bLoB + off);
                    mma16816(acc[nt], ah, bh);
                    mma16816(acc[nt], ah, bl);
                    mma16816(acc[nt], al, bh);
                }
            }
        }

        // gates = acc + xproj  -> sG
#pragma unroll
        for (int nt = 0; nt < 2; nt++) {
            int col = cg * 16 + nt * 8 + tq * 2;
            int q = col >> 3, jj = col & 7;
            int bA = r0 + g, bB = bA + 8;
            size_t xb = (size_t)t * B_ * G_ + (size_t)q * H_ + jbase + jj;
            float2 xA = *(const float2*)&xproj[xb + (size_t)bA * G_];
            float2 xB = *(const float2*)&xproj[xb + (size_t)bB * G_];
            sG[bA * 32 + col]     = acc[nt][0] + xA.x;
            sG[bA * 32 + col + 1] = acc[nt][1] + xA.y;
            sG[bB * 32 + col]     = acc[nt][2] + xB.x;
            sG[bB * 32 + col + 1] = acc[nt][3] + xB.y;
        }
        __syncthreads();

        // cell update: 512 cells/block
        __nv_bfloat16* hwH = g_hhi[(t + 1) & 1];
        __nv_bfloat16* hwL = g_hlo[(t + 1) & 1];
#pragma unroll
        for (int u = 0; u < 2; u++) {
            int id = tid + 256 * u;
            int b = id >> 3, jj = id & 7;
            float iv = sG[b * 32 + jj];
            float fv = sG[b * 32 + 8 + jj];
            float gv = sG[b * 32 + 16 + jj];
            float ov = sG[b * 32 + 24 + jj];
            float ig = 1.f / (1.f + expf(-iv));
            float fg = 1.f / (1.f + expf(-fv));
            float gg = tanhf(gv);
            float og = 1.f / (1.f + expf(-ov));
            float cc = fg * sC[b * 8 + jj] + ig * gg;
            sC[b * 8 + jj] = cc;
            float hh = og * tanhf(cc);
            __nv_bfloat16 hb = __float2bfloat16(hh);
            __nv_bfloat16 lb = __float2bfloat16(hh - __bfloat162float(hb));
            int hidx = b * H_ + jbase + jj;
            hwH[hidx] = hb; hwL[hidx] = lb;
            size_t sidx = ((size_t)t * B_ + b) * H_ + jbase + jj;
            hshi[sidx] = hb; hslo[sidx] = lb;
            if (writeLast && t == T_ - 1) g_hlast[hidx] = hh;
        }
        gridbar(&target);
    }
}

// ---------------- FC head ----------------
__global__ __launch_bounds__(256) void fc_kernel(
    const float* __restrict__ fc_w, const float* __restrict__ fc_b,
    float* __restrict__ out)
{
    __shared__ float sh[H_];
    int b = blockIdx.x, tid = threadIdx.x;
    const float* hlast = g_hlast + (size_t)b * H_;
    for (int i = tid; i < H_; i += 256) sh[i] = hlast[i];
    __syncthreads();
    int o = tid;
    const float* wrow = fc_w + (size_t)o * H_;
    float acc = fc_b[o];
#pragma unroll 8
    for (int k = 0; k < H_; k++) acc += sh[k] * wrow[k];
    out[b * O_ + o] = acc;
}

// ---------------- launch ----------------
#define SMEM_REC (2*(32*1032*2) + 2*(64*136*2) + 64*32*4 + 64*8*4)

extern "C" void kernel_launch(void* const* d_in, const int* in_sizes, int n_in,
                              void* d_out, int out_size) {
    (void)in_sizes; (void)n_in; (void)out_size;
    const float* x     = (const float*)d_in[0];
    const float* W_ih0 = (const float*)d_in[1];
    const float* W_hh0 = (const float*)d_in[2];
    const float* b_ih0 = (const float*)d_in[3];
    const float* b_hh0 = (const float*)d_in[4];
    const float* W_ih1 = (const float*)d_in[5];
    const float* W_hh1 = (const float*)d_in[6];
    const float* b_ih1 = (const float*)d_in[7];
    const float* b_hh1 = (const float*)d_in[8];
    const float* fc_w  = (const float*)d_in[9];
    const float* fc_b  = (const float*)d_in[10];
    float* out = (float*)d_out;

    float *xp0, *xp1;
    __nv_bfloat16 *xhi, *xlo, *w0hi, *w0lo, *w1hi, *w1lo, *hs0hi, *hs0lo;
    cudaGetSymbolAddress((void**)&xp0, g_xproj0);
    cudaGetSymbolAddress((void**)&xp1, g_xproj1);
    cudaGetSymbolAddress((void**)&xhi, g_xhi);
    cudaGetSymbolAddress((void**)&xlo, g_xlo);
    cudaGetSymbolAddress((void**)&w0hi, g_wih0hi);
    cudaGetSymbolAddress((void**)&w0lo, g_wih0lo);
    cudaGetSymbolAddress((void**)&w1hi, g_wih1hi);
    cudaGetSymbolAddress((void**)&w1lo, g_wih1lo);
    cudaGetSymbolAddress((void**)&hs0hi, g_hs0hi);
    cudaGetSymbolAddress((void**)&hs0lo, g_hs0lo);

    cudaFuncSetAttribute(lstm_recur_mma,
        cudaFuncAttributeMaxDynamicSharedMemorySize, SMEM_REC);

    // splits
    int nx4 = B_ * T_ * I_ / 4;
    split_kernel<<<(nx4 + 255) / 256, 256>>>(x, xhi, xlo, nx4);
    int nw04 = G_ * I_ / 4;
    split_kernel<<<(nw04 + 255) / 256, 256>>>(W_ih0, w0hi, w0lo, nw04);
    int nw14 = G_ * H_ / 4;
    split_kernel<<<(nw14 + 255) / 256, 256>>>(W_ih1, w1hi, w1lo, nw14);

    dim3 pgrid(G_ / 64, (B_ * T_) / 128);

    // layer 0
    mma_xproj<<<pgrid, 256>>>(xhi, xlo, w0hi, w0lo, b_ih0, b_hh0, xp0, I_, 0);
    init_kernel<<<64, 256>>>();
    lstm_recur_mma<<<128, 256, SMEM_REC>>>(xp0, W_hh0, hs0hi, hs0lo, 0);

    // layer 1
    mma_xproj<<<pgrid, 256>>>(hs0hi, hs0lo, w1hi, w1lo, b_ih1, b_hh1, xp1, H_, 1);
    init_kernel<<<64, 256>>>();
    // layer-1 hseq is only needed for its last step (kept fp32 in g_hlast);
    // reuse hs0 buffers as a write sink (hs0 already consumed by proj above).
    lstm_recur_mma<<<128, 256, SMEM_REC>>>(xp1, W_hh1, hs0hi, hs0lo, 1);

    // head
    fc_kernel<<<64, 256>>>(fc_w, fc_b, out);
}

// round 6
// speedup vs baseline: 2.5146x; 1.1924x over previous
#include <cuda_runtime.h>
#include <cuda_bf16.h>
#include <stdint.h>
#include <math.h>

#define B_ 64
#define T_ 512
#define I_ 256
#define H_ 1024
#define G_ 4096
#define O_ 256

// ---------------- device scratch ----------------
__device__ float g_xproj0[(size_t)T_ * B_ * G_];   // [t][b][4H] fp32
__device__ float g_xproj1[(size_t)T_ * B_ * G_];
__device__ __nv_bfloat16 g_xhi[(size_t)B_ * T_ * I_];
__device__ __nv_bfloat16 g_xlo[(size_t)B_ * T_ * I_];
__device__ __nv_bfloat16 g_wih0hi[(size_t)G_ * I_];
__device__ __nv_bfloat16 g_wih0lo[(size_t)G_ * I_];
__device__ __nv_bfloat16 g_wih1hi[(size_t)G_ * H_];
__device__ __nv_bfloat16 g_wih1lo[(size_t)G_ * H_];
__device__ __nv_bfloat16 g_hs0hi[(size_t)T_ * B_ * H_];  // layer-0 outputs hi/lo
__device__ __nv_bfloat16 g_hs0lo[(size_t)T_ * B_ * H_];
__device__ __nv_bfloat16 g_hhi[2][B_ * H_];
__device__ __nv_bfloat16 g_hlo[2][B_ * H_];
__device__ float g_hlast[B_ * H_];                 // fp32 final h for FC
__device__ unsigned int g_arrive;

// ---------------- helpers ----------------
__device__ __forceinline__ void ldsm4(uint32_t* r, uint32_t addr) {
    asm volatile("ldmatrix.sync.aligned.m8n8.x4.shared.b16 {%0,%1,%2,%3}, [%4];"
        : "=r"(r[0]), "=r"(r[1]), "=r"(r[2]), "=r"(r[3]) : "r"(addr));
}
__device__ __forceinline__ void ldsm2(uint32_t* r, uint32_t addr) {
    asm volatile("ldmatrix.sync.aligned.m8n8.x2.shared.b16 {%0,%1}, [%2];"
        : "=r"(r[0]), "=r"(r[1]) : "r"(addr));
}
__device__ __forceinline__ void mma16816(float* c, const uint32_t* a, const uint32_t* b) {
    asm volatile("mma.sync.aligned.m16n8k16.row.col.f32.bf16.bf16.f32 "
        "{%0,%1,%2,%3}, {%4,%5,%6,%7}, {%8,%9}, {%0,%1,%2,%3};"
        : "+f"(c[0]), "+f"(c[1]), "+f"(c[2]), "+f"(c[3])
        : "r"(a[0]), "r"(a[1]), "r"(a[2]), "r"(a[3]), "r"(b[0]), "r"(b[1]));
}
__device__ __forceinline__ uint32_t cvta_s(const void* p) {
    return (uint32_t)__cvta_generic_to_shared(p);
}
#define CP_ASYNC16(d, s) asm volatile("cp.async.cg.shared.global [%0], [%1], 16;" :: "r"(d), "l"(s))
#define CP_COMMIT()      asm volatile("cp.async.commit_group;" ::: "memory")
#define CP_WAIT1()       asm volatile("cp.async.wait_group 1;" ::: "memory")
#define CP_WAIT0()       asm volatile("cp.async.wait_group 0;" ::: "memory")

// ---------------- init ----------------
__global__ void init_kernel() {
    int idx = blockIdx.x * blockDim.x + threadIdx.x;
    if (idx == 0) g_arrive = 0u;
    __nv_bfloat16 z = __float2bfloat16(0.f);
    int n = 2 * B_ * H_;
    __nv_bfloat16* ph = (__nv_bfloat16*)g_hhi;
    __nv_bfloat16* pl = (__nv_bfloat16*)g_hlo;
    for (int i = idx; i < n; i += gridDim.x * blockDim.x) { ph[i] = z; pl[i] = z; }
}

// ---------------- fp32 -> bf16 hi/lo split ----------------
__global__ void split_kernel(const float* __restrict__ src,
                             __nv_bfloat16* __restrict__ hi,
                             __nv_bfloat16* __restrict__ lo, int n4) {
    int i = blockIdx.x * blockDim.x + threadIdx.x;
    if (i >= n4) return;
    float4 v = ((const float4*)src)[i];
    __nv_bfloat16 h0 = __float2bfloat16(v.x);
    __nv_bfloat16 h1 = __float2bfloat16(v.y);
    __nv_bfloat16 h2 = __float2bfloat16(v.z);
    __nv_bfloat16 h3 = __float2bfloat16(v.w);
    __nv_bfloat162 a, b;
    a.x = h0; a.y = h1; b.x = h2; b.y = h3;
    ((__nv_bfloat162*)hi)[2 * i] = a;
    ((__nv_bfloat162*)hi)[2 * i + 1] = b;
    a.x = __float2bfloat16(v.x - __bfloat162float(h0));
    a.y = __float2bfloat16(v.y - __bfloat162float(h1));
    b.x = __float2bfloat16(v.z - __bfloat162float(h2));
    b.y = __float2bfloat16(v.w - __bfloat162float(h3));
    ((__nv_bfloat162*)lo)[2 * i] = a;
    ((__nv_bfloat162*)lo)[2 * i + 1] = b;
}

// ---------------- software grid barrier ----------------
__device__ __forceinline__ void gridbar(unsigned int* target) {
    __threadfence();
    __syncthreads();
    if (threadIdx.x == 0) {
        atomicAdd(&g_arrive, 1u);
        *target += gridDim.x;
        unsigned int v;
        for (;;) {
            asm volatile("ld.acquire.gpu.u32 %0, [%1];" : "=r"(v) : "l"(&g_arrive) : "memory");
            if (v >= *target) break;
            __nanosleep(64);
        }
    }
    __syncthreads();
}

// ---------------- split-bf16 MMA projection GEMM ----------------
__global__ __launch_bounds__(256) void mma_xproj(
    const __nv_bfloat16* __restrict__ Ahi, const __nv_bfloat16* __restrict__ Alo,
    const __nv_bfloat16* __restrict__ Whi, const __nv_bfloat16* __restrict__ Wlo,
    const float* __restrict__ b1, const float* __restrict__ b2,
    float* __restrict__ Cout, int K, int mode)
{
    __shared__ __nv_bfloat16 sAhi[128 * 40], sAlo[128 * 40];
    __shared__ __nv_bfloat16 sBhi[64 * 40],  sBlo[64 * 40];
    __shared__ float sBias[64];

    int tid = threadIdx.x;
    int n0 = blockIdx.x * 64;
    int m0 = blockIdx.y * 128;
    int w = tid >> 5, lane = tid & 31;
    int r0 = w * 16;

    if (tid < 64) sBias[tid] = b1[n0 + tid] + b2[n0 + tid];

    float acc[8][4];
#pragma unroll
    for (int i = 0; i < 8; i++)
#pragma unroll
        for (int j = 0; j < 4; j++) acc[i][j] = 0.f;

    size_t arow[2]; int aoff[2];
#pragma unroll
    for (int it = 0; it < 2; it++) {
        int idx = tid + it * 256;
        int r = idx >> 2, seg = idx & 3;
        int m = m0 + r;
        arow[it] = (mode == 0) ? ((size_t)(m & 63) * T_ + (size_t)(m >> 6)) * (size_t)K + (size_t)(seg * 8)
                               : (size_t)m * (size_t)K + (size_t)(seg * 8);
        aoff[it] = r * 40 + seg * 8;
    }
    int br = tid >> 2, bseg = tid & 3;
    size_t brow = (size_t)(n0 + br) * (size_t)K + (size_t)(bseg * 8);
    int boff = br * 40 + bseg * 8;

    int lrA = (lane & 7) + (lane & 8);
    int lcA = (lane & 16) ? 8 : 0;
    uint32_t aHiB = cvta_s(&sAhi[(r0 + lrA) * 40 + lcA]);
    uint32_t aLoB = cvta_s(&sAlo[(r0 + lrA) * 40 + lcA]);
    int lrB = lane & 7;
    int lcB = (lane & 8) ? 8 : 0;
    uint32_t bHiB = cvta_s(&sBhi[lrB * 40 + lcB]);
    uint32_t bLoB = cvta_s(&sBlo[lrB * 40 + lcB]);

    for (int kc = 0; kc < K; kc += 32) {
        __syncthreads();
#pragma unroll
        for (int it = 0; it < 2; it++) {
            *(uint4*)&sAhi[aoff[it]] = *(const uint4*)(Ahi + arow[it] + kc);
            *(uint4*)&sAlo[aoff[it]] = *(const uint4*)(Alo + arow[it] + kc);
        }
        *(uint4*)&sBhi[boff] = *(const uint4*)(Whi + brow + kc);
        *(uint4*)&sBlo[boff] = *(const uint4*)(Wlo + brow + kc);
        __syncthreads();
#pragma unroll
        for (int ks = 0; ks < 2; ks++) {
            int k0 = ks * 16;
            uint32_t ah[4], al[4];
            ldsm4(ah, aHiB + (uint32_t)(k0 * 2));
            ldsm4(al, aLoB + (uint32_t)(k0 * 2));
#pragma unroll
            for (int nt = 0; nt < 8; nt++) {
                uint32_t bh[2], bl[2];
                uint32_t off = (uint32_t)(nt * 8 * 40 + k0) * 2u;
                ldsm2(bh, bHiB + off);
                ldsm2(bl, bLoB + off);
                mma16816(acc[nt], ah, bh);
                mma16816(acc[nt], ah, bl);
                mma16816(acc[nt], al, bh);
            }
        }
    }

    int g = lane >> 2, tq = lane & 3;
#pragma unroll
    for (int nt = 0; nt < 8; nt++) {
        int col = nt * 8 + tq * 2;
        float bb0 = sBias[col], bb1 = sBias[col + 1];
        size_t mA = (size_t)(m0 + r0 + g) * G_ + n0 + col;
        size_t mB = (size_t)(m0 + r0 + g + 8) * G_ + n0 + col;
        float2 v0 = make_float2(acc[nt][0] + bb0, acc[nt][1] + bb1);
        float2 v1 = make_float2(acc[nt][2] + bb0, acc[nt][3] + bb1);
        *(float2*)&Cout[mA] = v0;
        *(float2*)&Cout[mB] = v1;
    }
}

// ---------------- persistent LSTM recurrence (split-bf16 MMA, cp.async) ------
// 128 blocks x 512 threads (16 warps: 4 row-groups x 4 col-groups).
// Block owns 8 h-columns across all 4 gates (32 gate-cols).
// W_hh hi/lo resident in SMEM; h chunks double-buffered via cp.async.
extern __shared__ char smem_dyn[];
__global__ __launch_bounds__(512) void lstm_recur_mma(
    const float* __restrict__ xproj,   // [T][B][4H] fp32
    const float* __restrict__ Whh,     // [4H][H] fp32
    __nv_bfloat16* __restrict__ hshi, __nv_bfloat16* __restrict__ hslo,
    int writeSeq, int writeLast)
{
    __nv_bfloat16* sWhi = (__nv_bfloat16*)smem_dyn;        // 32 x 1032
    __nv_bfloat16* sWlo = sWhi + 32 * 1032;
    __nv_bfloat16* sH   = sWlo + 32 * 1032;                // 2 bufs x (hi,lo) x 64x136
    float* sG = (float*)(sH + 2 * 17408);                  // 64 x 32
    float* sC = sG + 64 * 32;                              // 64 x 8

    int tid = threadIdx.x, w = tid >> 5, lane = tid & 31;
    int jbase = blockIdx.x * 8;

    // load + split W_hh into SMEM (once)
    for (int i = tid; i < 32 * 1024; i += 512) {
        int n = i >> 10, k = i & 1023;
        float v = Whh[(size_t)((n >> 3) * H_ + jbase + (n & 7)) * H_ + k];
        __nv_bfloat16 hh = __float2bfloat16(v);
        sWhi[n * 1032 + k] = hh;
        sWlo[n * 1032 + k] = __float2bfloat16(v - __bfloat162float(hh));
    }
    for (int i = tid; i < 512; i += 512) sC[i] = 0.f;

    int r0 = (w & 3) * 16;   // batch-row group (16 rows)
    int cg = w >> 2;         // column group (0..3), 8 gate-cols each
    int lrA = (lane & 7) + (lane & 8);
    int lcA = (lane & 16) ? 8 : 0;
    uint32_t aHiB[2], aLoB[2], dstHi[2], dstLo[2];
#pragma unroll
    for (int bf = 0; bf < 2; bf++) {
        aHiB[bf] = cvta_s(&sH[bf * 17408 + (r0 + lrA) * 136 + lcA]);
        aLoB[bf] = cvta_s(&sH[bf * 17408 + 8704 + (r0 + lrA) * 136 + lcA]);
        dstHi[bf] = cvta_s(&sH[bf * 17408]);
        dstLo[bf] = cvta_s(&sH[bf * 17408 + 8704]);
    }
    int lrB = lane & 7;
    int lcB = (lane & 8) ? 8 : 0;
    uint32_t bHiB = cvta_s(&sWhi[lrB * 1032 + lcB]);
    uint32_t bLoB = cvta_s(&sWlo[lrB * 1032 + lcB]);

    // cp.async per-thread mapping: 2 x 16B per array per chunk
    int pr[2], ps[2];
#pragma unroll
    for (int it = 0; it < 2; it++) {
        int idx = tid + it * 512;
        pr[it] = idx >> 4;            // row 0..63
        ps[it] = (idx & 15) * 8;      // col segment (elements)
    }

    unsigned int target = 0;
    int g = lane >> 2, tq = lane & 3;
    int col = cg * 8 + tq * 2;        // gate-col 0..31
    int q = col >> 3, jj = col & 7;
    int bA = r0 + g, bB = bA + 8;

    __syncthreads();

    for (int t = 0; t < T_; t++) {
        const __nv_bfloat16* hrH = g_hhi[t & 1];
        const __nv_bfloat16* hrL = g_hlo[t & 1];

        // prefetch chunk 0
#pragma unroll
        for (int it = 0; it < 2; it++) {
            uint32_t so = (uint32_t)(pr[it] * 136 + ps[it]) * 2u;
            CP_ASYNC16(dstHi[0] + so, hrH + pr[it] * H_ + ps[it]);
            CP_ASYNC16(dstLo[0] + so, hrL + pr[it] * H_ + ps[it]);
        }
        CP_COMMIT();

        // hoist xproj loads (DRAM latency hidden behind k-loop)
        size_t xb = (size_t)t * B_ * G_ + (size_t)q * H_ + jbase + jj;
        float2 xA = *(const float2*)&xproj[xb + (size_t)bA * G_];
        float2 xB = *(const float2*)&xproj[xb + (size_t)bB * G_];

        float acc[4];
#pragma unroll
        for (int j = 0; j < 4; j++) acc[j] = 0.f;

        for (int ch = 0; ch < 8; ch++) {
            int cur = ch & 1;
            if (ch < 7) {
                int kc2 = (ch + 1) * 128;
#pragma unroll
                for (int it = 0; it < 2; it++) {
                    uint32_t so = (uint32_t)(pr[it] * 136 + ps[it]) * 2u;
                    CP_ASYNC16(dstHi[cur ^ 1] + so, hrH + pr[it] * H_ + kc2 + ps[it]);
                    CP_ASYNC16(dstLo[cur ^ 1] + so, hrL + pr[it] * H_ + kc2 + ps[it]);
                }
                CP_COMMIT();
                CP_WAIT1();
            } else {
                CP_WAIT0();
            }
            __syncthreads();

            int kc = ch * 128;
#pragma unroll
            for (int ks = 0; ks < 8; ks++) {
                int k0 = ks * 16;
                uint32_t ah[4], al[4];
                ldsm4(ah, aHiB[cur] + (uint32_t)(k0 * 2));
                ldsm4(al, aLoB[cur] + (uint32_t)(k0 * 2));
                uint32_t bh[2], bl[2];
                uint32_t off = (uint32_t)(cg * 8 * 1032 + kc + k0) * 2u;
                ldsm2(bh, bHiB + off);
                ldsm2(bl, bLoB + off);
                mma16816(acc, ah, bh);
                mma16816(acc, ah, bl);
                mma16816(acc, al, bh);
            }
            __syncthreads();
        }

        // gates = acc + xproj  -> sG
        sG[bA * 32 + col]     = acc[0] + xA.x;
        sG[bA * 32 + col + 1] = acc[1] + xA.y;
        sG[bB * 32 + col]     = acc[2] + xB.x;
        sG[bB * 32 + col + 1] = acc[3] + xB.y;
        __syncthreads();

        // cell update: 512 cells/block, 1 per thread
        __nv_bfloat16* hwH = g_hhi[(t + 1) & 1];
        __nv_bfloat16* hwL = g_hlo[(t + 1) & 1];
        {
            int b = tid >> 3, j2 = tid & 7;
            float iv = sG[b * 32 + j2];
            float fv = sG[b * 32 + 8 + j2];
            float gv = sG[b * 32 + 16 + j2];
            float ov = sG[b * 32 + 24 + j2];
            float ig = 1.f / (1.f + expf(-iv));
            float fg = 1.f / (1.f + expf(-fv));
            float gg = tanhf(gv);
            float og = 1.f / (1.f + expf(-ov));
            float cc = fg * sC[b * 8 + j2] + ig * gg;
            sC[b * 8 + j2] = cc;
            float hh = og * tanhf(cc);
            __nv_bfloat16 hb = __float2bfloat16(hh);
            __nv_bfloat16 lb = __float2bfloat16(hh - __bfloat162float(hb));
            int hidx = b * H_ + jbase + j2;
            hwH[hidx] = hb; hwL[hidx] = lb;
            if (writeSeq) {
                size_t sidx = ((size_t)t * B_ + b) * H_ + jbase + j2;
                hshi[sidx] = hb; hslo[sidx] = lb;
            }
            if (writeLast && t == T_ - 1) g_hlast[hidx] = hh;
        }
        gridbar(&target);
    }
}

// ---------------- FC head ----------------
__global__ __launch_bounds__(256) void fc_kernel(
    const float* __restrict__ fc_w, const float* __restrict__ fc_b,
    float* __restrict__ out)
{
    __shared__ float sh[H_];
    int b = blockIdx.x, tid = threadIdx.x;
    const float* hlast = g_hlast + (size_t)b * H_;
    for (int i = tid; i < H_; i += 256) sh[i] = hlast[i];
    __syncthreads();
    int o = tid;
    const float* wrow = fc_w + (size_t)o * H_;
    float acc = fc_b[o];
#pragma unroll 8
    for (int k = 0; k < H_; k++) acc += sh[k] * wrow[k];
    out[b * O_ + o] = acc;
}

// ---------------- launch ----------------
#define SMEM_REC ((32*1032*2 + 2*17408) * 2 + 64*32*4 + 64*8*4)

extern "C" void kernel_launch(void* const* d_in, const int* in_sizes, int n_in,
                              void* d_out, int out_size) {
    (void)in_sizes; (void)n_in; (void)out_size;
    const float* x     = (const float*)d_in[0];
    const float* W_ih0 = (const float*)d_in[1];
    const float* W_hh0 = (const float*)d_in[2];
    const float* b_ih0 = (const float*)d_in[3];
    const float* b_hh0 = (const float*)d_in[4];
    const float* W_ih1 = (const float*)d_in[5];
    const float* W_hh1 = (const float*)d_in[6];
    const float* b_ih1 = (const float*)d_in[7];
    const float* b_hh1 = (const float*)d_in[8];
    const float* fc_w  = (const float*)d_in[9];
    const float* fc_b  = (const float*)d_in[10];
    float* out = (float*)d_out;

    float *xp0, *xp1;
    __nv_bfloat16 *xhi, *xlo, *w0hi, *w0lo, *w1hi, *w1lo, *hs0hi, *hs0lo;
    cudaGetSymbolAddress((void**)&xp0, g_xproj0);
    cudaGetSymbolAddress((void**)&xp1, g_xproj1);
    cudaGetSymbolAddress((void**)&xhi, g_xhi);
    cudaGetSymbolAddress((void**)&xlo, g_xlo);
    cudaGetSymbolAddress((void**)&w0hi, g_wih0hi);
    cudaGetSymbolAddress((void**)&w0lo, g_wih0lo);
    cudaGetSymbolAddress((void**)&w1hi, g_wih1hi);
    cudaGetSymbolAddress((void**)&w1lo, g_wih1lo);
    cudaGetSymbolAddress((void**)&hs0hi, g_hs0hi);
    cudaGetSymbolAddress((void**)&hs0lo, g_hs0lo);

    cudaFuncSetAttribute(lstm_recur_mma,
        cudaFuncAttributeMaxDynamicSharedMemorySize, SMEM_REC);

    // splits
    int nx4 = B_ * T_ * I_ / 4;
    split_kernel<<<(nx4 + 255) / 256, 256>>>(x, xhi, xlo, nx4);
    int nw04 = G_ * I_ / 4;
    split_kernel<<<(nw04 + 255) / 256, 256>>>(W_ih0, w0hi, w0lo, nw04);
    int nw14 = G_ * H_ / 4;
    split_kernel<<<(nw14 + 255) / 256, 256>>>(W_ih1, w1hi, w1lo, nw14);

    dim3 pgrid(G_ / 64, (B_ * T_) / 128);

    // layer 0
    mma_xproj<<<pgrid, 256>>>(xhi, xlo, w0hi, w0lo, b_ih0, b_hh0, xp0, I_, 0);
    init_kernel<<<64, 256>>>();
    lstm_recur_mma<<<128, 512, SMEM_REC>>>(xp0, W_hh0, hs0hi, hs0lo, 1, 0);

    // layer 1
    mma_xproj<<<pgrid, 256>>>(hs0hi, hs0lo, w1hi, w1lo, b_ih1, b_hh1, xp1, H_, 1);
    init_kernel<<<64, 256>>>();
    lstm_recur_mma<<<128, 512, SMEM_REC>>>(xp1, W_hh1, hs0hi, hs0lo, 0, 1);

    // head
    fc_kernel<<<64, 256>>>(fc_w, fc_b, out);
}